// round 13
// baseline (speedup 1.0000x reference)
#include <cuda_runtime.h>
#include <cuda_bf16.h>
#include <float.h>

// Problem constants (fixed by the dataset)
#define NMAX 50000
#define EMAX 800000
#define HD   128   // H*D
#define H8   8

typedef unsigned long long u64;

// ---------------- scratch (device globals; no allocation allowed) ----------
__device__ float g_hf   [NMAX * HD];   // nfeat @ W_fc
__device__ float g_S    [NMAX * HD];   // normalized attention aggregate
__device__ float g_Esum [NMAX * HD];   // segment_sum(efeat, dst)
__device__ float g_el   [NMAX * H8];
__device__ float g_er   [NMAX * H8];
__device__ float g_indeg[NMAX];
// CSR build
__device__ int  g_cnt [NMAX];
__device__ int  g_off [NMAX + 1];
__device__ int  g_pos [NMAX];
__device__ int  g_bsum[64];
__device__ int2 g_edge[EMAX];          // (eid, src) grouped by dst

// ---------------- f32x2 helpers ---------------------------------------------
__device__ __forceinline__ void ffma2(u64& d, u64 a, u64 b) {
    asm("fma.rn.f32x2 %0, %1, %2, %3;" : "=l"(d) : "l"(a), "l"(b), "l"(d));
}
__device__ __forceinline__ u64 pack_bcast(float x) {
    u64 r;
    asm("mov.b64 %0, {%1, %1};" : "=l"(r) : "r"(__float_as_uint(x)));
    return r;
}
__device__ __forceinline__ float2 unpack_f32x2(u64 v) {
    unsigned int lo, hi;
    asm("mov.b64 {%0, %1}, %2;" : "=r"(lo), "=r"(hi) : "l"(v));
    return make_float2(__uint_as_float(lo), __uint_as_float(hi));
}

// ---------------- CSR build kernels -----------------------------------------
__global__ void zero_cnt_kernel(int N) {
    int i = blockIdx.x * blockDim.x + threadIdx.x;
    if (i < N) g_cnt[i] = 0;
}

__global__ void hist_kernel(const int* __restrict__ dst, int E) {
    int e = blockIdx.x * blockDim.x + threadIdx.x;
    if (e < E) atomicAdd(&g_cnt[dst[e]], 1);
}

// block-level inclusive scan (1024/block), exclusive written to g_off
__global__ void __launch_bounds__(1024) scan1_kernel(int N) {
    __shared__ int sm[1024];
    int i = blockIdx.x * 1024 + threadIdx.x;
    int v = (i < N) ? g_cnt[i] : 0;
    sm[threadIdx.x] = v;
    __syncthreads();
    #pragma unroll
    for (int off = 1; off < 1024; off <<= 1) {
        int t = (threadIdx.x >= off) ? sm[threadIdx.x - off] : 0;
        __syncthreads();
        sm[threadIdx.x] += t;
        __syncthreads();
    }
    if (i < N) g_off[i] = sm[threadIdx.x] - v;
    if (threadIdx.x == 1023) g_bsum[blockIdx.x] = sm[1023];
}

// scan3 with block-sum prefix folded in (64-thread Hillis-Steele per block)
__global__ void scan3_kernel(int nb, int E, int N) {
    __shared__ int sincl[64];
    __shared__ int sexcl[64];
    int tid = threadIdx.x;
    int v = 0;
    if (tid < 64) {
        v = (tid < nb) ? g_bsum[tid] : 0;
        sincl[tid] = v;
    }
    __syncthreads();
    #pragma unroll
    for (int off = 1; off < 64; off <<= 1) {
        int t = (tid >= off && tid < 64) ? sincl[tid - off] : 0;
        __syncthreads();
        if (tid < 64) sincl[tid] += t;
        __syncthreads();
    }
    if (tid < 64) sexcl[tid] = sincl[tid] - v;
    __syncthreads();
    int i = blockIdx.x * blockDim.x + tid;
    if (i < N) {
        int o = g_off[i] + sexcl[i >> 10];
        g_off[i] = o;
        g_pos[i] = o;
    }
    if (blockIdx.x == 0 && tid == 0) g_off[N] = E;
}

__global__ void scatter_eid_kernel(const int* __restrict__ src,
                                   const int* __restrict__ dst, int E) {
    int e = blockIdx.x * blockDim.x + threadIdx.x;
    if (e >= E) return;
    int d = dst[e];
    int p = atomicAdd(&g_pos[d], 1);
    g_edge[p] = make_int2(e, src[e]);
}

// ---------------- 128x128 GEMM over node rows (FFMA2 inner loop) ------------
// MODE 0: hf = nfeat @ W_fc ; epilogue computes el/er
// MODE 1: tmp = Esum @ W_e  ; epilogue combines everything into out
// rowoff: starting row of this launch (64-aligned); nrows: global row limit.
template <int MODE>
__global__ void __launch_bounds__(256) gemm128_kernel(
    const float* __restrict__ Xin, const float* __restrict__ W,
    int rowoff, int nrows,
    const float* __restrict__ attn_l, const float* __restrict__ attn_r,
    const float* __restrict__ bias,  const float* __restrict__ b_e,
    float* __restrict__ out)
{
    extern __shared__ float sm[];
    float*  Wsm  = sm;                 // 128*128
    float*  Xsm  = sm + HD * HD;       // 64*128
    __shared__ float attnsm[256];      // [attn_l(128) | attn_r(128)]

    const float* X = (MODE == 0) ? Xin : (const float*)g_Esum;

    int tid = threadIdx.x;

    const float4* W4 = (const float4*)W;
    float4* Wsm4 = (float4*)Wsm;
    #pragma unroll
    for (int i = tid; i < 4096; i += 256) Wsm4[i] = W4[i];

    if (MODE == 0) {
        if (tid < 128) {
            attnsm[tid]       = attn_l[tid];
            attnsm[128 + tid] = attn_r[tid];
        }
    }

    int rowbase = rowoff + blockIdx.x * 64;

    const float4* X4 = (const float4*)X;
    float4* Xsm4 = (float4*)Xsm;
    #pragma unroll
    for (int i = tid; i < 2048; i += 256) {
        int r = i >> 5, c = i & 31;
        int gr = rowbase + r;
        Xsm4[i] = (gr < nrows) ? X4[(size_t)gr * 32 + c]
                               : make_float4(0.f, 0.f, 0.f, 0.f);
    }
    __syncthreads();

    int lane = tid & 31;
    int warp = tid >> 5;
    int r0   = warp * 8;

    // packed accumulators: acc2[r][0] = cols {4l,4l+1}, acc2[r][1] = cols {4l+2,4l+3}
    u64 acc2[8][2];
    #pragma unroll
    for (int r = 0; r < 8; r++) { acc2[r][0] = 0ull; acc2[r][1] = 0ull; }

    const ulonglong2* Wsm2 = (const ulonglong2*)Wsm;
    for (int k4 = 0; k4 < HD; k4 += 4) {
        float4 xr[8];
        #pragma unroll
        for (int r = 0; r < 8; r++)
            xr[r] = *(const float4*)&Xsm[(r0 + r) * HD + k4];
        #pragma unroll
        for (int kk = 0; kk < 4; kk++) {
            ulonglong2 w2 = Wsm2[(k4 + kk) * 32 + lane];
            #pragma unroll
            for (int r = 0; r < 8; r++) {
                float xv = (kk == 0) ? xr[r].x : (kk == 1) ? xr[r].y
                         : (kk == 2) ? xr[r].z : xr[r].w;
                u64 xx = pack_bcast(xv);
                ffma2(acc2[r][0], xx, w2.x);
                ffma2(acc2[r][1], xx, w2.y);
            }
        }
    }

    int h   = lane >> 2;          // head for these 4 cols
    int off = (lane & 3) * 4;     // offset within head (0..12)

    if (MODE == 0) {
        #pragma unroll
        for (int r = 0; r < 8; r++) {
            int gr = rowbase + r0 + r;
            if (gr >= nrows) break;
            float2 p0 = unpack_f32x2(acc2[r][0]);
            float2 p1 = unpack_f32x2(acc2[r][1]);
            float4 a  = make_float4(p0.x, p0.y, p1.x, p1.y);
            ((float4*)(g_hf + (size_t)gr * HD))[lane] = a;
            float pl = a.x * attnsm[h * 16 + off]
                     + a.y * attnsm[h * 16 + off + 1]
                     + a.z * attnsm[h * 16 + off + 2]
                     + a.w * attnsm[h * 16 + off + 3];
            float pr = a.x * attnsm[128 + h * 16 + off]
                     + a.y * attnsm[128 + h * 16 + off + 1]
                     + a.z * attnsm[128 + h * 16 + off + 2]
                     + a.w * attnsm[128 + h * 16 + off + 3];
            pl += __shfl_xor_sync(0xffffffffu, pl, 1);
            pl += __shfl_xor_sync(0xffffffffu, pl, 2);
            pr += __shfl_xor_sync(0xffffffffu, pr, 1);
            pr += __shfl_xor_sync(0xffffffffu, pr, 2);
            if ((lane & 3) == 0) {
                g_el[gr * H8 + h] = pl;
                g_er[gr * H8 + h] = pr;
            }
        }
    } else {
        #pragma unroll
        for (int r = 0; r < 8; r++) {
            int gr = rowbase + r0 + r;
            if (gr >= nrows) break;
            float2 p0 = unpack_f32x2(acc2[r][0]);
            float2 p1 = unpack_f32x2(acc2[r][1]);
            float4 a  = make_float4(p0.x, p0.y, p1.x, p1.y);
            float indeg = g_indeg[gr];
            float4 S4   = ((const float4*)(g_S  + (size_t)gr * HD))[lane]; // pre-normalized
            float4 hf4  = ((const float4*)(g_hf + (size_t)gr * HD))[lane];
            float4 b4   = ((const float4*)bias)[lane];
            float4 be4  = ((const float4*)b_e)[lane];
            float  rs   = 1.f / (indeg + 1.f);
            float  rme  = 1.f / fmaxf(indeg, 1.f);
            float4 o;
            o.x = S4.x + b4.x + hf4.x * rs + (a.x + indeg * be4.x) * rme;
            o.y = S4.y + b4.y + hf4.y * rs + (a.y + indeg * be4.y) * rme;
            o.z = S4.z + b4.z + hf4.z * rs + (a.z + indeg * be4.z) * rme;
            o.w = S4.w + b4.w + hf4.w * rs + (a.w + indeg * be4.w) * rme;
            ((float4*)(out + (size_t)gr * HD))[lane] = o;
        }
    }
}

// ---------------- fused per-node gather (softmax + aggregate + Esum) --------
// One warp per dst node, edges grouped by dst via CSR. Node range [n0, n1).
// Softmax without max subtraction (shift-invariant; scores are O(1) here).
// 4-wide software pipeline: 8 independent LDG.128 in flight per iteration.
__global__ void __launch_bounds__(256) gather_kernel(
    const float* __restrict__ efeat, int n0, int n1)
{
    int gtid = blockIdx.x * blockDim.x + threadIdx.x;
    int n    = n0 + (gtid >> 5);
    int lane = gtid & 31;
    if (n >= n1) return;

    int beg = g_off[n];
    int end = g_off[n + 1];

    float er_l = 0.f;
    if (lane < 8) er_l = g_er[n * H8 + lane];

    float  denom = 0.f;
    float4 accS  = make_float4(0.f, 0.f, 0.f, 0.f);
    float4 accE  = make_float4(0.f, 0.f, 0.f, 0.f);

    const float4* hf4 = (const float4*)g_hf;
    const float4* ef4 = (const float4*)efeat;

    int j = beg;
    for (; j + 3 < end; j += 4) {
        int2 a = g_edge[j];
        int2 b = g_edge[j + 1];
        int2 c = g_edge[j + 2];
        int2 d = g_edge[j + 3];
        // issue all 8 big loads up front (MLP)
        float4 hv0 = __ldg(&hf4[(size_t)a.y * 32 + lane]);
        float4 hv1 = __ldg(&hf4[(size_t)b.y * 32 + lane]);
        float4 hv2 = __ldg(&hf4[(size_t)c.y * 32 + lane]);
        float4 hv3 = __ldg(&hf4[(size_t)d.y * 32 + lane]);
        float4 ev0 = __ldg(&ef4[(size_t)a.x * 32 + lane]);
        float4 ev1 = __ldg(&ef4[(size_t)b.x * 32 + lane]);
        float4 ev2 = __ldg(&ef4[(size_t)c.x * 32 + lane]);
        float4 ev3 = __ldg(&ef4[(size_t)d.x * 32 + lane]);
        float ex0 = 0.f, ex1 = 0.f, ex2 = 0.f, ex3 = 0.f;
        if (lane < 8) {
            float s0 = g_el[a.y * H8 + lane] + er_l;
            float s1 = g_el[b.y * H8 + lane] + er_l;
            float s2 = g_el[c.y * H8 + lane] + er_l;
            float s3 = g_el[d.y * H8 + lane] + er_l;
            s0 = s0 >= 0.f ? s0 : 0.2f * s0;
            s1 = s1 >= 0.f ? s1 : 0.2f * s1;
            s2 = s2 >= 0.f ? s2 : 0.2f * s2;
            s3 = s3 >= 0.f ? s3 : 0.2f * s3;
            ex0 = __expf(s0);
            ex1 = __expf(s1);
            ex2 = __expf(s2);
            ex3 = __expf(s3);
            denom += (ex0 + ex1) + (ex2 + ex3);
        }
        float e0 = __shfl_sync(0xffffffffu, ex0, lane >> 2);
        float e1 = __shfl_sync(0xffffffffu, ex1, lane >> 2);
        float e2 = __shfl_sync(0xffffffffu, ex2, lane >> 2);
        float e3 = __shfl_sync(0xffffffffu, ex3, lane >> 2);
        accS.x += e0 * hv0.x + e1 * hv1.x + e2 * hv2.x + e3 * hv3.x;
        accS.y += e0 * hv0.y + e1 * hv1.y + e2 * hv2.y + e3 * hv3.y;
        accS.z += e0 * hv0.z + e1 * hv1.z + e2 * hv2.z + e3 * hv3.z;
        accS.w += e0 * hv0.w + e1 * hv1.w + e2 * hv2.w + e3 * hv3.w;
        accE.x += (ev0.x + ev1.x) + (ev2.x + ev3.x);
        accE.y += (ev0.y + ev1.y) + (ev2.y + ev3.y);
        accE.z += (ev0.z + ev1.z) + (ev2.z + ev3.z);
        accE.w += (ev0.w + ev1.w) + (ev2.w + ev3.w);
    }
    for (; j < end; j++) {
        int2 a = g_edge[j];
        float4 hv0 = __ldg(&hf4[(size_t)a.y * 32 + lane]);
        float4 ev0 = __ldg(&ef4[(size_t)a.x * 32 + lane]);
        float ex0 = 0.f;
        if (lane < 8) {
            float s0 = g_el[a.y * H8 + lane] + er_l;
            s0 = s0 >= 0.f ? s0 : 0.2f * s0;
            ex0 = __expf(s0);
            denom += ex0;
        }
        float e0 = __shfl_sync(0xffffffffu, ex0, lane >> 2);
        accS.x += e0 * hv0.x;
        accS.y += e0 * hv0.y;
        accS.z += e0 * hv0.z;
        accS.w += e0 * hv0.w;
        accE.x += ev0.x;
        accE.y += ev0.y;
        accE.z += ev0.z;
        accE.w += ev0.w;
    }

    float rd  = (denom > 0.f) ? (1.f / denom) : 0.f;   // valid on lanes 0-7
    float rdh = __shfl_sync(0xffffffffu, rd, lane >> 2);
    accS.x *= rdh; accS.y *= rdh; accS.z *= rdh; accS.w *= rdh;

    ((float4*)g_S)   [(size_t)n * 32 + lane] = accS;
    ((float4*)g_Esum)[(size_t)n * 32 + lane] = accE;
    if (lane == 0) g_indeg[n] = (float)(end - beg);
}

// ---------------- launch ----------------------------------------------------
extern "C" void kernel_launch(void* const* d_in, const int* in_sizes, int n_in,
                              void* d_out, int out_size)
{
    const float* nfeat  = (const float*)d_in[0];
    const float* efeat  = (const float*)d_in[1];
    const int*   src    = (const int*)  d_in[2];
    const int*   dst    = (const int*)  d_in[3];
    const float* W_fc   = (const float*)d_in[4];
    const float* attn_l = (const float*)d_in[5];
    const float* attn_r = (const float*)d_in[6];
    const float* bias   = (const float*)d_in[7];
    const float* W_e    = (const float*)d_in[8];
    const float* b_e    = (const float*)d_in[9];
    float*       out    = (float*)d_out;

    int N = in_sizes[0] / HD;
    int E = in_sizes[2];
    if (N > NMAX) N = NMAX;
    if (E > EMAX) E = EMAX;

    const int SMEM = (HD * HD + 64 * HD) * (int)sizeof(float);  // 96KB
    cudaFuncSetAttribute((const void*)gemm128_kernel<0>,
                         cudaFuncAttributeMaxDynamicSharedMemorySize, SMEM);
    cudaFuncSetAttribute((const void*)gemm128_kernel<1>,
                         cudaFuncAttributeMaxDynamicSharedMemorySize, SMEM);

    // side stream + fork/join events (created once; reused every call so the
    // captured work is identical on every invocation)
    static cudaStream_t s2 = nullptr;
    static cudaEvent_t  evFork = nullptr, evCSR = nullptr,
                        evH0 = nullptr, evH1 = nullptr, evDone = nullptr;
    if (s2 == nullptr) {
        cudaStreamCreateWithFlags(&s2, cudaStreamNonBlocking);
        cudaEventCreateWithFlags(&evFork, cudaEventDisableTiming);
        cudaEventCreateWithFlags(&evCSR,  cudaEventDisableTiming);
        cudaEventCreateWithFlags(&evH0,   cudaEventDisableTiming);
        cudaEventCreateWithFlags(&evH1,   cudaEventDisableTiming);
        cudaEventCreateWithFlags(&evDone, cudaEventDisableTiming);
    }

    int nb = (N + 1023) / 1024;

    // node split at a 64-row boundary (so GEMM1 halves tile cleanly)
    int N2 = ((N / 2 + 63) / 64) * 64;
    if (N2 > N) N2 = N;
    int blocksH0 = (N2 + 63) / 64;              // rows [0, N2)
    int blocksH1 = (N + 63) / 64 - blocksH0;    // rows [N2, N)

    // ---- fork: CSR build on s2, node GEMM on main stream (independent) ----
    cudaEventRecord(evFork, 0);
    cudaStreamWaitEvent(s2, evFork, 0);

    zero_cnt_kernel<<<(N + 255) / 256, 256, 0, s2>>>(N);
    hist_kernel<<<(E + 255) / 256, 256, 0, s2>>>(dst, E);
    scan1_kernel<<<nb, 1024, 0, s2>>>(N);
    scan3_kernel<<<(N + 255) / 256, 256, 0, s2>>>(nb, E, N);
    scatter_eid_kernel<<<(E + 255) / 256, 256, 0, s2>>>(src, dst, E);
    cudaEventRecord(evCSR, s2);

    // node GEMM (hf, el, er) on main stream, concurrent with CSR build
    gemm128_kernel<0><<<(N + 63) / 64, 256, SMEM>>>(
        nfeat, W_fc, 0, N, attn_l, attn_r, nullptr, nullptr, nullptr);

    // ---- pipelined gather / edge-GEMM over two node halves ----
    cudaStreamWaitEvent(0, evCSR, 0);

    // gather half 0 on main
    gather_kernel<<<(N2 * 32 + 255) / 256, 256>>>(efeat, 0, N2);
    cudaEventRecord(evH0, 0);

    // gather half 1 on main (runs concurrent with GEMM1 half 0 on s2)
    if (N > N2) {
        gather_kernel<<<((N - N2) * 32 + 255) / 256, 256>>>(efeat, N2, N);
    }
    cudaEventRecord(evH1, 0);

    // edge GEMM half 0 on s2 (after gather half 0; transitively after GEMM0)
    cudaStreamWaitEvent(s2, evH0, 0);
    gemm128_kernel<1><<<blocksH0, 256, SMEM, s2>>>(
        nullptr, W_e, 0, N2, nullptr, nullptr, bias, b_e, out);

    // edge GEMM half 1 on s2 (after gather half 1)
    cudaStreamWaitEvent(s2, evH1, 0);
    if (blocksH1 > 0) {
        gemm128_kernel<1><<<blocksH1, 256, SMEM, s2>>>(
            nullptr, W_e, N2, N, nullptr, nullptr, bias, b_e, out);
    }
    cudaEventRecord(evDone, s2);

    // join s2 back into the capture origin stream
    cudaStreamWaitEvent(0, evDone, 0);
}

// round 15
// speedup vs baseline: 1.0069x; 1.0069x over previous
#include <cuda_runtime.h>
#include <cuda_bf16.h>
#include <float.h>

// Problem constants (fixed by the dataset)
#define NMAX 50000
#define EMAX 800000
#define HD   128   // H*D
#define H8   8

typedef unsigned long long u64;

// ---------------- scratch (device globals; no allocation allowed) ----------
__device__ float g_hf   [NMAX * HD];   // nfeat @ W_fc
__device__ float g_S    [NMAX * HD];   // normalized attention aggregate
__device__ float g_Esum [NMAX * HD];   // segment_sum(efeat, dst)
__device__ float g_el   [NMAX * H8];
__device__ float g_er   [NMAX * H8];
__device__ float g_indeg[NMAX];
// CSR build
__device__ int  g_cnt [NMAX];
__device__ int  g_off [NMAX + 1];
__device__ int  g_pos [NMAX];
__device__ int  g_bsum[64];
__device__ int2 g_edge[EMAX];          // (eid, src) grouped by dst

// ---------------- f32x2 helpers ---------------------------------------------
__device__ __forceinline__ void ffma2(u64& d, u64 a, u64 b) {
    asm("fma.rn.f32x2 %0, %1, %2, %3;" : "=l"(d) : "l"(a), "l"(b), "l"(d));
}
__device__ __forceinline__ u64 pack2(float lo, float hi) {
    u64 r;
    asm("mov.b64 %0, {%1, %2};" : "=l"(r) : "r"(__float_as_uint(lo)), "r"(__float_as_uint(hi)));
    return r;
}
__device__ __forceinline__ float2 unpack_f32x2(u64 v) {
    unsigned int lo, hi;
    asm("mov.b64 {%0, %1}, %2;" : "=r"(lo), "=r"(hi) : "l"(v));
    return make_float2(__uint_as_float(lo), __uint_as_float(hi));
}

// ---------------- CSR build kernels -----------------------------------------
__global__ void zero_cnt_kernel(int N) {
    int i = blockIdx.x * blockDim.x + threadIdx.x;
    if (i < N) g_cnt[i] = 0;
}

__global__ void hist_kernel(const int* __restrict__ dst, int E) {
    int e = blockIdx.x * blockDim.x + threadIdx.x;
    if (e < E) atomicAdd(&g_cnt[dst[e]], 1);
}

// block-level inclusive scan (1024/block), exclusive written to g_off
__global__ void __launch_bounds__(1024) scan1_kernel(int N) {
    __shared__ int sm[1024];
    int i = blockIdx.x * 1024 + threadIdx.x;
    int v = (i < N) ? g_cnt[i] : 0;
    sm[threadIdx.x] = v;
    __syncthreads();
    #pragma unroll
    for (int off = 1; off < 1024; off <<= 1) {
        int t = (threadIdx.x >= off) ? sm[threadIdx.x - off] : 0;
        __syncthreads();
        sm[threadIdx.x] += t;
        __syncthreads();
    }
    if (i < N) g_off[i] = sm[threadIdx.x] - v;
    if (threadIdx.x == 1023) g_bsum[blockIdx.x] = sm[1023];
}

// scan3 with block-sum prefix folded in (64-thread Hillis-Steele per block)
__global__ void scan3_kernel(int nb, int E, int N) {
    __shared__ int sincl[64];
    __shared__ int sexcl[64];
    int tid = threadIdx.x;
    int v = 0;
    if (tid < 64) {
        v = (tid < nb) ? g_bsum[tid] : 0;
        sincl[tid] = v;
    }
    __syncthreads();
    #pragma unroll
    for (int off = 1; off < 64; off <<= 1) {
        int t = (tid >= off && tid < 64) ? sincl[tid - off] : 0;
        __syncthreads();
        if (tid < 64) sincl[tid] += t;
        __syncthreads();
    }
    if (tid < 64) sexcl[tid] = sincl[tid] - v;
    __syncthreads();
    int i = blockIdx.x * blockDim.x + tid;
    if (i < N) {
        int o = g_off[i] + sexcl[i >> 10];
        g_off[i] = o;
        g_pos[i] = o;
    }
    if (blockIdx.x == 0 && tid == 0) g_off[N] = E;
}

__global__ void scatter_eid_kernel(const int* __restrict__ src,
                                   const int* __restrict__ dst, int E) {
    int e = blockIdx.x * blockDim.x + threadIdx.x;
    if (e >= E) return;
    int d = dst[e];
    int p = atomicAdd(&g_pos[d], 1);
    g_edge[p] = make_int2(e, src[e]);
}

// ---------------- 128x128 GEMM over node rows (K-split FFMA2) ---------------
// MODE 0: hf = nfeat @ W_fc ; epilogue computes el/er
// MODE 1: tmp = Esum @ W_e  ; epilogue combines everything into out
// 256 threads = 8 warps; warp handles 8 rows; lane handles cols 4l..4l+3.
// Tile = 64 rows. smem: W interleaved (64KB) + X tile (32KB) = 96KB dynamic.
// W smem layout: Wsm2[kp*128 + c] = {W[2kp][c], W[2kp+1][c]} (u64, kp=0..63).
// FFMA2 does 2 k's at once; acc halves = even/odd-k partials, summed at end.
template <int MODE>
__global__ void __launch_bounds__(256) gemm128_kernel(
    const float* __restrict__ Xin, const float* __restrict__ W, int nrows,
    const float* __restrict__ attn_l, const float* __restrict__ attn_r,
    const float* __restrict__ bias,  const float* __restrict__ b_e,
    float* __restrict__ out)
{
    extern __shared__ float sm[];
    u64*    Wsm2 = (u64*)sm;           // 64*128 u64 = 64KB
    float*  Xsm  = sm + HD * HD;       // 64*128 f32 = 32KB
    __shared__ float attnsm[256];      // [attn_l(128) | attn_r(128)]

    const float* X = (MODE == 0) ? Xin : (const float*)g_Esum;

    int tid = threadIdx.x;

    // W load: interleave pairs of k-rows. Task i: kp = i>>5, col-group cg = i&31.
    const float4* W4 = (const float4*)W;
    #pragma unroll
    for (int i = tid; i < 2048; i += 256) {
        int kp = i >> 5;
        int cg = i & 31;
        float4 wa = W4[(2 * kp) * 32 + cg];       // row 2kp, cols 4cg..4cg+3
        float4 wb = W4[(2 * kp + 1) * 32 + cg];   // row 2kp+1
        u64* dst64 = &Wsm2[kp * 128 + cg * 4];
        dst64[0] = pack2(wa.x, wb.x);
        dst64[1] = pack2(wa.y, wb.y);
        dst64[2] = pack2(wa.z, wb.z);
        dst64[3] = pack2(wa.w, wb.w);
    }

    if (MODE == 0) {
        if (tid < 128) {
            attnsm[tid]       = attn_l[tid];
            attnsm[128 + tid] = attn_r[tid];
        }
    }

    int rowbase = blockIdx.x * 64;

    const float4* X4 = (const float4*)X;
    float4* Xsm4 = (float4*)Xsm;
    #pragma unroll
    for (int i = tid; i < 2048; i += 256) {
        int r = i >> 5, c = i & 31;
        int gr = rowbase + r;
        Xsm4[i] = (gr < nrows) ? X4[(size_t)gr * 32 + c]
                               : make_float4(0.f, 0.f, 0.f, 0.f);
    }
    __syncthreads();

    int lane = tid & 31;
    int warp = tid >> 5;
    int r0   = warp * 8;

    // acc2[r][j]: col 4*lane+j; halves hold even-k / odd-k partial sums
    u64 acc2[8][4];
    #pragma unroll
    for (int r = 0; r < 8; r++) {
        acc2[r][0] = 0ull; acc2[r][1] = 0ull;
        acc2[r][2] = 0ull; acc2[r][3] = 0ull;
    }

    for (int kp = 0; kp < 64; kp++) {
        // W for this k-pair: 4 u64 (32B) per lane, contiguous
        ulonglong2 wA = *(const ulonglong2*)&Wsm2[kp * 128 + 4 * lane];
        ulonglong2 wB = *(const ulonglong2*)&Wsm2[kp * 128 + 4 * lane + 2];
        #pragma unroll
        for (int r = 0; r < 8; r++) {
            // {x[r][2kp], x[r][2kp+1]} adjacent in smem -> LDS.64 broadcast
            u64 xx = *(const u64*)&Xsm[(r0 + r) * HD + 2 * kp];
            ffma2(acc2[r][0], xx, wA.x);
            ffma2(acc2[r][1], xx, wA.y);
            ffma2(acc2[r][2], xx, wB.x);
            ffma2(acc2[r][3], xx, wB.y);
        }
    }

    int h   = lane >> 2;          // head for these 4 cols
    int off = (lane & 3) * 4;     // offset within head (0..12)

    if (MODE == 0) {
        #pragma unroll
        for (int r = 0; r < 8; r++) {
            int gr = rowbase + r0 + r;
            if (gr >= nrows) break;
            float2 q0 = unpack_f32x2(acc2[r][0]);
            float2 q1 = unpack_f32x2(acc2[r][1]);
            float2 q2 = unpack_f32x2(acc2[r][2]);
            float2 q3 = unpack_f32x2(acc2[r][3]);
            float4 a = make_float4(q0.x + q0.y, q1.x + q1.y,
                                   q2.x + q2.y, q3.x + q3.y);
            ((float4*)(g_hf + (size_t)gr * HD))[lane] = a;
            float pl = a.x * attnsm[h * 16 + off]
                     + a.y * attnsm[h * 16 + off + 1]
                     + a.z * attnsm[h * 16 + off + 2]
                     + a.w * attnsm[h * 16 + off + 3];
            float pr = a.x * attnsm[128 + h * 16 + off]
                     + a.y * attnsm[128 + h * 16 + off + 1]
                     + a.z * attnsm[128 + h * 16 + off + 2]
                     + a.w * attnsm[128 + h * 16 + off + 3];
            pl += __shfl_xor_sync(0xffffffffu, pl, 1);
            pl += __shfl_xor_sync(0xffffffffu, pl, 2);
            pr += __shfl_xor_sync(0xffffffffu, pr, 1);
            pr += __shfl_xor_sync(0xffffffffu, pr, 2);
            if ((lane & 3) == 0) {
                g_el[gr * H8 + h] = pl;
                g_er[gr * H8 + h] = pr;
            }
        }
    } else {
        #pragma unroll
        for (int r = 0; r < 8; r++) {
            int gr = rowbase + r0 + r;
            if (gr >= nrows) break;
            float2 q0 = unpack_f32x2(acc2[r][0]);
            float2 q1 = unpack_f32x2(acc2[r][1]);
            float2 q2 = unpack_f32x2(acc2[r][2]);
            float2 q3 = unpack_f32x2(acc2[r][3]);
            float4 a = make_float4(q0.x + q0.y, q1.x + q1.y,
                                   q2.x + q2.y, q3.x + q3.y);
            float indeg = g_indeg[gr];
            float4 S4   = ((const float4*)(g_S  + (size_t)gr * HD))[lane]; // pre-normalized
            float4 hf4  = ((const float4*)(g_hf + (size_t)gr * HD))[lane];
            float4 b4   = ((const float4*)bias)[lane];
            float4 be4  = ((const float4*)b_e)[lane];
            float  rs   = 1.f / (indeg + 1.f);
            float  rme  = 1.f / fmaxf(indeg, 1.f);
            float4 o;
            o.x = S4.x + b4.x + hf4.x * rs + (a.x + indeg * be4.x) * rme;
            o.y = S4.y + b4.y + hf4.y * rs + (a.y + indeg * be4.y) * rme;
            o.z = S4.z + b4.z + hf4.z * rs + (a.z + indeg * be4.z) * rme;
            o.w = S4.w + b4.w + hf4.w * rs + (a.w + indeg * be4.w) * rme;
            ((float4*)(out + (size_t)gr * HD))[lane] = o;
        }
    }
}

// ---------------- fused per-node gather (softmax + aggregate + Esum) --------
// One warp per dst node, edges grouped by dst via CSR.
// Softmax without max subtraction (shift-invariant; scores are O(1) here).
// 4-wide software pipeline: 8 independent LDG.128 in flight per iteration.
__global__ void __launch_bounds__(256) gather_kernel(
    const float* __restrict__ efeat, int N)
{
    int gtid = blockIdx.x * blockDim.x + threadIdx.x;
    int n    = gtid >> 5;
    int lane = gtid & 31;
    if (n >= N) return;

    int beg = g_off[n];
    int end = g_off[n + 1];

    float er_l = 0.f;
    if (lane < 8) er_l = g_er[n * H8 + lane];

    float  denom = 0.f;
    float4 accS  = make_float4(0.f, 0.f, 0.f, 0.f);
    float4 accE  = make_float4(0.f, 0.f, 0.f, 0.f);

    const float4* hf4 = (const float4*)g_hf;
    const float4* ef4 = (const float4*)efeat;

    int j = beg;
    for (; j + 3 < end; j += 4) {
        int2 a = g_edge[j];
        int2 b = g_edge[j + 1];
        int2 c = g_edge[j + 2];
        int2 d = g_edge[j + 3];
        // issue all 8 big loads up front (MLP)
        float4 hv0 = __ldg(&hf4[(size_t)a.y * 32 + lane]);
        float4 hv1 = __ldg(&hf4[(size_t)b.y * 32 + lane]);
        float4 hv2 = __ldg(&hf4[(size_t)c.y * 32 + lane]);
        float4 hv3 = __ldg(&hf4[(size_t)d.y * 32 + lane]);
        float4 ev0 = __ldg(&ef4[(size_t)a.x * 32 + lane]);
        float4 ev1 = __ldg(&ef4[(size_t)b.x * 32 + lane]);
        float4 ev2 = __ldg(&ef4[(size_t)c.x * 32 + lane]);
        float4 ev3 = __ldg(&ef4[(size_t)d.x * 32 + lane]);
        float ex0 = 0.f, ex1 = 0.f, ex2 = 0.f, ex3 = 0.f;
        if (lane < 8) {
            float s0 = g_el[a.y * H8 + lane] + er_l;
            float s1 = g_el[b.y * H8 + lane] + er_l;
            float s2 = g_el[c.y * H8 + lane] + er_l;
            float s3 = g_el[d.y * H8 + lane] + er_l;
            s0 = s0 >= 0.f ? s0 : 0.2f * s0;
            s1 = s1 >= 0.f ? s1 : 0.2f * s1;
            s2 = s2 >= 0.f ? s2 : 0.2f * s2;
            s3 = s3 >= 0.f ? s3 : 0.2f * s3;
            ex0 = __expf(s0);
            ex1 = __expf(s1);
            ex2 = __expf(s2);
            ex3 = __expf(s3);
            denom += (ex0 + ex1) + (ex2 + ex3);
        }
        float e0 = __shfl_sync(0xffffffffu, ex0, lane >> 2);
        float e1 = __shfl_sync(0xffffffffu, ex1, lane >> 2);
        float e2 = __shfl_sync(0xffffffffu, ex2, lane >> 2);
        float e3 = __shfl_sync(0xffffffffu, ex3, lane >> 2);
        accS.x += e0 * hv0.x + e1 * hv1.x + e2 * hv2.x + e3 * hv3.x;
        accS.y += e0 * hv0.y + e1 * hv1.y + e2 * hv2.y + e3 * hv3.y;
        accS.z += e0 * hv0.z + e1 * hv1.z + e2 * hv2.z + e3 * hv3.z;
        accS.w += e0 * hv0.w + e1 * hv1.w + e2 * hv2.w + e3 * hv3.w;
        accE.x += (ev0.x + ev1.x) + (ev2.x + ev3.x);
        accE.y += (ev0.y + ev1.y) + (ev2.y + ev3.y);
        accE.z += (ev0.z + ev1.z) + (ev2.z + ev3.z);
        accE.w += (ev0.w + ev1.w) + (ev2.w + ev3.w);
    }
    for (; j < end; j++) {
        int2 a = g_edge[j];
        float4 hv0 = __ldg(&hf4[(size_t)a.y * 32 + lane]);
        float4 ev0 = __ldg(&ef4[(size_t)a.x * 32 + lane]);
        float ex0 = 0.f;
        if (lane < 8) {
            float s0 = g_el[a.y * H8 + lane] + er_l;
            s0 = s0 >= 0.f ? s0 : 0.2f * s0;
            ex0 = __expf(s0);
            denom += ex0;
        }
        float e0 = __shfl_sync(0xffffffffu, ex0, lane >> 2);
        accS.x += e0 * hv0.x;
        accS.y += e0 * hv0.y;
        accS.z += e0 * hv0.z;
        accS.w += e0 * hv0.w;
        accE.x += ev0.x;
        accE.y += ev0.y;
        accE.z += ev0.z;
        accE.w += ev0.w;
    }

    float rd  = (denom > 0.f) ? (1.f / denom) : 0.f;   // valid on lanes 0-7
    float rdh = __shfl_sync(0xffffffffu, rd, lane >> 2);
    accS.x *= rdh; accS.y *= rdh; accS.z *= rdh; accS.w *= rdh;

    ((float4*)g_S)   [(size_t)n * 32 + lane] = accS;
    ((float4*)g_Esum)[(size_t)n * 32 + lane] = accE;
    if (lane == 0) g_indeg[n] = (float)(end - beg);
}

// ---------------- launch ----------------------------------------------------
extern "C" void kernel_launch(void* const* d_in, const int* in_sizes, int n_in,
                              void* d_out, int out_size)
{
    const float* nfeat  = (const float*)d_in[0];
    const float* efeat  = (const float*)d_in[1];
    const int*   src    = (const int*)  d_in[2];
    const int*   dst    = (const int*)  d_in[3];
    const float* W_fc   = (const float*)d_in[4];
    const float* attn_l = (const float*)d_in[5];
    const float* attn_r = (const float*)d_in[6];
    const float* bias   = (const float*)d_in[7];
    const float* W_e    = (const float*)d_in[8];
    const float* b_e    = (const float*)d_in[9];
    float*       out    = (float*)d_out;

    int N = in_sizes[0] / HD;
    int E = in_sizes[2];
    if (N > NMAX) N = NMAX;
    if (E > EMAX) E = EMAX;

    const int SMEM = (HD * HD + 64 * HD) * (int)sizeof(float);  // 96KB
    cudaFuncSetAttribute((const void*)gemm128_kernel<0>,
                         cudaFuncAttributeMaxDynamicSharedMemorySize, SMEM);
    cudaFuncSetAttribute((const void*)gemm128_kernel<1>,
                         cudaFuncAttributeMaxDynamicSharedMemorySize, SMEM);

    // side stream + fork/join events (created once; reused every call so the
    // captured work is identical on every invocation)
    static cudaStream_t s2 = nullptr;
    static cudaEvent_t  evFork = nullptr, evJoin = nullptr;
    if (s2 == nullptr) {
        cudaStreamCreateWithFlags(&s2, cudaStreamNonBlocking);
        cudaEventCreateWithFlags(&evFork, cudaEventDisableTiming);
        cudaEventCreateWithFlags(&evJoin, cudaEventDisableTiming);
    }

    int nb = (N + 1023) / 1024;

    // ---- fork: CSR build on s2, node GEMM on main stream (independent) ----
    cudaEventRecord(evFork, 0);
    cudaStreamWaitEvent(s2, evFork, 0);

    zero_cnt_kernel<<<(N + 255) / 256, 256, 0, s2>>>(N);
    hist_kernel<<<(E + 255) / 256, 256, 0, s2>>>(dst, E);
    scan1_kernel<<<nb, 1024, 0, s2>>>(N);
    scan3_kernel<<<(N + 255) / 256, 256, 0, s2>>>(nb, E, N);
    scatter_eid_kernel<<<(E + 255) / 256, 256, 0, s2>>>(src, dst, E);
    cudaEventRecord(evJoin, s2);

    // node GEMM (hf, el, er) on main stream, concurrent with CSR build
    gemm128_kernel<0><<<(N + 63) / 64, 256, SMEM>>>(
        nfeat, W_fc, N, attn_l, attn_r, nullptr, nullptr, nullptr);

    // ---- join: gather needs both CSR and GEMM0 ----
    cudaStreamWaitEvent(0, evJoin, 0);

    // fused softmax + aggregation + edge-feature sum
    gather_kernel<<<(N * 32 + 255) / 256, 256>>>(efeat, N);

    // edge GEMM (reordered through segment-sum) + final combine
    gemm128_kernel<1><<<(N + 63) / 64, 256, SMEM>>>(
        nullptr, W_e, N, nullptr, nullptr, bias, b_e, out);
}

// round 16
// speedup vs baseline: 1.0653x; 1.0581x over previous
#include <cuda_runtime.h>
#include <cuda_bf16.h>
#include <cuda_fp16.h>
#include <float.h>

// Problem constants (fixed by the dataset)
#define NMAX 50000
#define EMAX 800000
#define HD   128   // H*D
#define H8   8

typedef unsigned long long u64;

// ---------------- scratch (device globals; no allocation allowed) ----------
__device__ float g_hf   [NMAX * HD];   // nfeat @ W_fc (fp32, for GEMM1 epilogue)
__device__ uint2 g_hf16 [NMAX * 32];   // fp16 shadow of hf (4 halves per uint2)
__device__ float g_S    [NMAX * HD];   // normalized attention aggregate
__device__ float g_Esum [NMAX * HD];   // segment_sum(efeat, dst)
__device__ float g_el   [NMAX * H8];
__device__ float g_er   [NMAX * H8];
__device__ float g_indeg[NMAX];
// CSR build
__device__ int  g_cnt [NMAX];
__device__ int  g_off [NMAX + 1];
__device__ int  g_pos [NMAX];
__device__ int  g_bsum[64];
__device__ int2 g_edge[EMAX];          // (eid, src) grouped by dst

// ---------------- f32x2 helpers ---------------------------------------------
__device__ __forceinline__ void ffma2(u64& d, u64 a, u64 b) {
    asm("fma.rn.f32x2 %0, %1, %2, %3;" : "=l"(d) : "l"(a), "l"(b), "l"(d));
}
__device__ __forceinline__ u64 pack_bcast(float x) {
    u64 r;
    asm("mov.b64 %0, {%1, %1};" : "=l"(r) : "r"(__float_as_uint(x)));
    return r;
}
__device__ __forceinline__ float2 unpack_f32x2(u64 v) {
    unsigned int lo, hi;
    asm("mov.b64 {%0, %1}, %2;" : "=r"(lo), "=r"(hi) : "l"(v));
    return make_float2(__uint_as_float(lo), __uint_as_float(hi));
}

// ---------------- CSR build kernels -----------------------------------------
__global__ void zero_cnt_kernel(int N) {
    int i = blockIdx.x * blockDim.x + threadIdx.x;
    if (i < N) g_cnt[i] = 0;
}

__global__ void hist_kernel(const int* __restrict__ dst, int E) {
    int e = blockIdx.x * blockDim.x + threadIdx.x;
    if (e < E) atomicAdd(&g_cnt[dst[e]], 1);
}

// block-level inclusive scan (1024/block), exclusive written to g_off
__global__ void __launch_bounds__(1024) scan1_kernel(int N) {
    __shared__ int sm[1024];
    int i = blockIdx.x * 1024 + threadIdx.x;
    int v = (i < N) ? g_cnt[i] : 0;
    sm[threadIdx.x] = v;
    __syncthreads();
    #pragma unroll
    for (int off = 1; off < 1024; off <<= 1) {
        int t = (threadIdx.x >= off) ? sm[threadIdx.x - off] : 0;
        __syncthreads();
        sm[threadIdx.x] += t;
        __syncthreads();
    }
    if (i < N) g_off[i] = sm[threadIdx.x] - v;
    if (threadIdx.x == 1023) g_bsum[blockIdx.x] = sm[1023];
}

// scan3 with block-sum prefix folded in (64-thread Hillis-Steele per block)
__global__ void scan3_kernel(int nb, int E, int N) {
    __shared__ int sincl[64];
    __shared__ int sexcl[64];
    int tid = threadIdx.x;
    int v = 0;
    if (tid < 64) {
        v = (tid < nb) ? g_bsum[tid] : 0;
        sincl[tid] = v;
    }
    __syncthreads();
    #pragma unroll
    for (int off = 1; off < 64; off <<= 1) {
        int t = (tid >= off && tid < 64) ? sincl[tid - off] : 0;
        __syncthreads();
        if (tid < 64) sincl[tid] += t;
        __syncthreads();
    }
    if (tid < 64) sexcl[tid] = sincl[tid] - v;
    __syncthreads();
    int i = blockIdx.x * blockDim.x + tid;
    if (i < N) {
        int o = g_off[i] + sexcl[i >> 10];
        g_off[i] = o;
        g_pos[i] = o;
    }
    if (blockIdx.x == 0 && tid == 0) g_off[N] = E;
}

__global__ void scatter_eid_kernel(const int* __restrict__ src,
                                   const int* __restrict__ dst, int E) {
    int e = blockIdx.x * blockDim.x + threadIdx.x;
    if (e >= E) return;
    int d = dst[e];
    int p = atomicAdd(&g_pos[d], 1);
    g_edge[p] = make_int2(e, src[e]);
}

// ---------------- 128x128 GEMM over node rows (FFMA2 inner loop) ------------
// MODE 0: hf = nfeat @ W_fc ; epilogue computes el/er + fp16 shadow of hf
// MODE 1: tmp = Esum @ W_e  ; epilogue combines everything into out
template <int MODE>
__global__ void __launch_bounds__(256) gemm128_kernel(
    const float* __restrict__ Xin, const float* __restrict__ W, int nrows,
    const float* __restrict__ attn_l, const float* __restrict__ attn_r,
    const float* __restrict__ bias,  const float* __restrict__ b_e,
    float* __restrict__ out)
{
    extern __shared__ float sm[];
    float*  Wsm  = sm;                 // 128*128
    float*  Xsm  = sm + HD * HD;       // 64*128
    __shared__ float attnsm[256];      // [attn_l(128) | attn_r(128)]

    const float* X = (MODE == 0) ? Xin : (const float*)g_Esum;

    int tid = threadIdx.x;

    const float4* W4 = (const float4*)W;
    float4* Wsm4 = (float4*)Wsm;
    #pragma unroll
    for (int i = tid; i < 4096; i += 256) Wsm4[i] = W4[i];

    if (MODE == 0) {
        if (tid < 128) {
            attnsm[tid]       = attn_l[tid];
            attnsm[128 + tid] = attn_r[tid];
        }
    }

    int rowbase = blockIdx.x * 64;

    const float4* X4 = (const float4*)X;
    float4* Xsm4 = (float4*)Xsm;
    #pragma unroll
    for (int i = tid; i < 2048; i += 256) {
        int r = i >> 5, c = i & 31;
        int gr = rowbase + r;
        Xsm4[i] = (gr < nrows) ? X4[(size_t)gr * 32 + c]
                               : make_float4(0.f, 0.f, 0.f, 0.f);
    }
    __syncthreads();

    int lane = tid & 31;
    int warp = tid >> 5;
    int r0   = warp * 8;

    // packed accumulators: acc2[r][0] = cols {4l,4l+1}, acc2[r][1] = cols {4l+2,4l+3}
    u64 acc2[8][2];
    #pragma unroll
    for (int r = 0; r < 8; r++) { acc2[r][0] = 0ull; acc2[r][1] = 0ull; }

    const ulonglong2* Wsm2 = (const ulonglong2*)Wsm;
    for (int k4 = 0; k4 < HD; k4 += 4) {
        float4 xr[8];
        #pragma unroll
        for (int r = 0; r < 8; r++)
            xr[r] = *(const float4*)&Xsm[(r0 + r) * HD + k4];
        #pragma unroll
        for (int kk = 0; kk < 4; kk++) {
            ulonglong2 w2 = Wsm2[(k4 + kk) * 32 + lane];
            #pragma unroll
            for (int r = 0; r < 8; r++) {
                float xv = (kk == 0) ? xr[r].x : (kk == 1) ? xr[r].y
                         : (kk == 2) ? xr[r].z : xr[r].w;
                u64 xx = pack_bcast(xv);
                ffma2(acc2[r][0], xx, w2.x);
                ffma2(acc2[r][1], xx, w2.y);
            }
        }
    }

    int h   = lane >> 2;          // head for these 4 cols
    int off = (lane & 3) * 4;     // offset within head (0..12)

    if (MODE == 0) {
        #pragma unroll
        for (int r = 0; r < 8; r++) {
            int gr = rowbase + r0 + r;
            if (gr >= nrows) break;
            float2 p0 = unpack_f32x2(acc2[r][0]);
            float2 p1 = unpack_f32x2(acc2[r][1]);
            float4 a  = make_float4(p0.x, p0.y, p1.x, p1.y);
            ((float4*)(g_hf + (size_t)gr * HD))[lane] = a;
            // fp16 shadow copy for the gather (halves its hf LTS traffic)
            {
                __half2 ha = __floats2half2_rn(a.x, a.y);
                __half2 hb = __floats2half2_rn(a.z, a.w);
                uint2 hv;
                hv.x = *(unsigned int*)&ha;
                hv.y = *(unsigned int*)&hb;
                g_hf16[(size_t)gr * 32 + lane] = hv;
            }
            float pl = a.x * attnsm[h * 16 + off]
                     + a.y * attnsm[h * 16 + off + 1]
                     + a.z * attnsm[h * 16 + off + 2]
                     + a.w * attnsm[h * 16 + off + 3];
            float pr = a.x * attnsm[128 + h * 16 + off]
                     + a.y * attnsm[128 + h * 16 + off + 1]
                     + a.z * attnsm[128 + h * 16 + off + 2]
                     + a.w * attnsm[128 + h * 16 + off + 3];
            pl += __shfl_xor_sync(0xffffffffu, pl, 1);
            pl += __shfl_xor_sync(0xffffffffu, pl, 2);
            pr += __shfl_xor_sync(0xffffffffu, pr, 1);
            pr += __shfl_xor_sync(0xffffffffu, pr, 2);
            if ((lane & 3) == 0) {
                g_el[gr * H8 + h] = pl;
                g_er[gr * H8 + h] = pr;
            }
        }
    } else {
        #pragma unroll
        for (int r = 0; r < 8; r++) {
            int gr = rowbase + r0 + r;
            if (gr >= nrows) break;
            float2 p0 = unpack_f32x2(acc2[r][0]);
            float2 p1 = unpack_f32x2(acc2[r][1]);
            float4 a  = make_float4(p0.x, p0.y, p1.x, p1.y);
            float indeg = g_indeg[gr];
            float4 S4   = ((const float4*)(g_S  + (size_t)gr * HD))[lane]; // pre-normalized
            float4 hf4  = ((const float4*)(g_hf + (size_t)gr * HD))[lane];
            float4 b4   = ((const float4*)bias)[lane];
            float4 be4  = ((const float4*)b_e)[lane];
            float  rs   = 1.f / (indeg + 1.f);
            float  rme  = 1.f / fmaxf(indeg, 1.f);
            float4 o;
            o.x = S4.x + b4.x + hf4.x * rs + (a.x + indeg * be4.x) * rme;
            o.y = S4.y + b4.y + hf4.y * rs + (a.y + indeg * be4.y) * rme;
            o.z = S4.z + b4.z + hf4.z * rs + (a.z + indeg * be4.z) * rme;
            o.w = S4.w + b4.w + hf4.w * rs + (a.w + indeg * be4.w) * rme;
            ((float4*)(out + (size_t)gr * HD))[lane] = o;
        }
    }
}

// ---------------- fused per-node gather (softmax + aggregate + Esum) --------
// One warp per dst node, edges grouped by dst via CSR.
// Softmax without max subtraction (shift-invariant; scores are O(1) here).
// hf read as fp16 shadow (halves LTS traffic); scores/denom/efeat stay fp32.
// 4-wide software pipeline: 8 independent loads in flight per iteration.
__global__ void __launch_bounds__(256) gather_kernel(
    const float* __restrict__ efeat, int N)
{
    int gtid = blockIdx.x * blockDim.x + threadIdx.x;
    int n    = gtid >> 5;
    int lane = gtid & 31;
    if (n >= N) return;

    int beg = g_off[n];
    int end = g_off[n + 1];

    float er_l = 0.f;
    if (lane < 8) er_l = g_er[n * H8 + lane];

    float  denom = 0.f;
    float4 accS  = make_float4(0.f, 0.f, 0.f, 0.f);
    float4 accE  = make_float4(0.f, 0.f, 0.f, 0.f);

    const float4* ef4 = (const float4*)efeat;

    int j = beg;
    for (; j + 3 < end; j += 4) {
        int2 a = g_edge[j];
        int2 b = g_edge[j + 1];
        int2 c = g_edge[j + 2];
        int2 d = g_edge[j + 3];
        // issue all 8 big loads up front (MLP)
        uint2  hv0 = __ldg(&g_hf16[(size_t)a.y * 32 + lane]);
        uint2  hv1 = __ldg(&g_hf16[(size_t)b.y * 32 + lane]);
        uint2  hv2 = __ldg(&g_hf16[(size_t)c.y * 32 + lane]);
        uint2  hv3 = __ldg(&g_hf16[(size_t)d.y * 32 + lane]);
        float4 ev0 = __ldg(&ef4[(size_t)a.x * 32 + lane]);
        float4 ev1 = __ldg(&ef4[(size_t)b.x * 32 + lane]);
        float4 ev2 = __ldg(&ef4[(size_t)c.x * 32 + lane]);
        float4 ev3 = __ldg(&ef4[(size_t)d.x * 32 + lane]);
        float ex0 = 0.f, ex1 = 0.f, ex2 = 0.f, ex3 = 0.f;
        if (lane < 8) {
            float s0 = g_el[a.y * H8 + lane] + er_l;
            float s1 = g_el[b.y * H8 + lane] + er_l;
            float s2 = g_el[c.y * H8 + lane] + er_l;
            float s3 = g_el[d.y * H8 + lane] + er_l;
            s0 = s0 >= 0.f ? s0 : 0.2f * s0;
            s1 = s1 >= 0.f ? s1 : 0.2f * s1;
            s2 = s2 >= 0.f ? s2 : 0.2f * s2;
            s3 = s3 >= 0.f ? s3 : 0.2f * s3;
            ex0 = __expf(s0);
            ex1 = __expf(s1);
            ex2 = __expf(s2);
            ex3 = __expf(s3);
            denom += (ex0 + ex1) + (ex2 + ex3);
        }
        float e0 = __shfl_sync(0xffffffffu, ex0, lane >> 2);
        float e1 = __shfl_sync(0xffffffffu, ex1, lane >> 2);
        float e2 = __shfl_sync(0xffffffffu, ex2, lane >> 2);
        float e3 = __shfl_sync(0xffffffffu, ex3, lane >> 2);
        float2 f0a = __half22float2(*(__half2*)&hv0.x);
        float2 f0b = __half22float2(*(__half2*)&hv0.y);
        float2 f1a = __half22float2(*(__half2*)&hv1.x);
        float2 f1b = __half22float2(*(__half2*)&hv1.y);
        float2 f2a = __half22float2(*(__half2*)&hv2.x);
        float2 f2b = __half22float2(*(__half2*)&hv2.y);
        float2 f3a = __half22float2(*(__half2*)&hv3.x);
        float2 f3b = __half22float2(*(__half2*)&hv3.y);
        accS.x += e0 * f0a.x + e1 * f1a.x + e2 * f2a.x + e3 * f3a.x;
        accS.y += e0 * f0a.y + e1 * f1a.y + e2 * f2a.y + e3 * f3a.y;
        accS.z += e0 * f0b.x + e1 * f1b.x + e2 * f2b.x + e3 * f3b.x;
        accS.w += e0 * f0b.y + e1 * f1b.y + e2 * f2b.y + e3 * f3b.y;
        accE.x += (ev0.x + ev1.x) + (ev2.x + ev3.x);
        accE.y += (ev0.y + ev1.y) + (ev2.y + ev3.y);
        accE.z += (ev0.z + ev1.z) + (ev2.z + ev3.z);
        accE.w += (ev0.w + ev1.w) + (ev2.w + ev3.w);
    }
    for (; j < end; j++) {
        int2 a = g_edge[j];
        uint2  hv0 = __ldg(&g_hf16[(size_t)a.y * 32 + lane]);
        float4 ev0 = __ldg(&ef4[(size_t)a.x * 32 + lane]);
        float ex0 = 0.f;
        if (lane < 8) {
            float s0 = g_el[a.y * H8 + lane] + er_l;
            s0 = s0 >= 0.f ? s0 : 0.2f * s0;
            ex0 = __expf(s0);
            denom += ex0;
        }
        float e0 = __shfl_sync(0xffffffffu, ex0, lane >> 2);
        float2 f0a = __half22float2(*(__half2*)&hv0.x);
        float2 f0b = __half22float2(*(__half2*)&hv0.y);
        accS.x += e0 * f0a.x;
        accS.y += e0 * f0a.y;
        accS.z += e0 * f0b.x;
        accS.w += e0 * f0b.y;
        accE.x += ev0.x;
        accE.y += ev0.y;
        accE.z += ev0.z;
        accE.w += ev0.w;
    }

    float rd  = (denom > 0.f) ? (1.f / denom) : 0.f;   // valid on lanes 0-7
    float rdh = __shfl_sync(0xffffffffu, rd, lane >> 2);
    accS.x *= rdh; accS.y *= rdh; accS.z *= rdh; accS.w *= rdh;

    ((float4*)g_S)   [(size_t)n * 32 + lane] = accS;
    ((float4*)g_Esum)[(size_t)n * 32 + lane] = accE;
    if (lane == 0) g_indeg[n] = (float)(end - beg);
}

// ---------------- launch ----------------------------------------------------
extern "C" void kernel_launch(void* const* d_in, const int* in_sizes, int n_in,
                              void* d_out, int out_size)
{
    const float* nfeat  = (const float*)d_in[0];
    const float* efeat  = (const float*)d_in[1];
    const int*   src    = (const int*)  d_in[2];
    const int*   dst    = (const int*)  d_in[3];
    const float* W_fc   = (const float*)d_in[4];
    const float* attn_l = (const float*)d_in[5];
    const float* attn_r = (const float*)d_in[6];
    const float* bias   = (const float*)d_in[7];
    const float* W_e    = (const float*)d_in[8];
    const float* b_e    = (const float*)d_in[9];
    float*       out    = (float*)d_out;

    int N = in_sizes[0] / HD;
    int E = in_sizes[2];
    if (N > NMAX) N = NMAX;
    if (E > EMAX) E = EMAX;

    const int SMEM = (HD * HD + 64 * HD) * (int)sizeof(float);  // 96KB
    cudaFuncSetAttribute((const void*)gemm128_kernel<0>,
                         cudaFuncAttributeMaxDynamicSharedMemorySize, SMEM);
    cudaFuncSetAttribute((const void*)gemm128_kernel<1>,
                         cudaFuncAttributeMaxDynamicSharedMemorySize, SMEM);

    // side stream + fork/join events (created once; reused every call so the
    // captured work is identical on every invocation)
    static cudaStream_t s2 = nullptr;
    static cudaEvent_t  evFork = nullptr, evJoin = nullptr;
    if (s2 == nullptr) {
        cudaStreamCreateWithFlags(&s2, cudaStreamNonBlocking);
        cudaEventCreateWithFlags(&evFork, cudaEventDisableTiming);
        cudaEventCreateWithFlags(&evJoin, cudaEventDisableTiming);
    }

    int nb = (N + 1023) / 1024;

    // ---- fork: CSR build on s2, node GEMM on main stream (independent) ----
    cudaEventRecord(evFork, 0);
    cudaStreamWaitEvent(s2, evFork, 0);

    zero_cnt_kernel<<<(N + 255) / 256, 256, 0, s2>>>(N);
    hist_kernel<<<(E + 255) / 256, 256, 0, s2>>>(dst, E);
    scan1_kernel<<<nb, 1024, 0, s2>>>(N);
    scan3_kernel<<<(N + 255) / 256, 256, 0, s2>>>(nb, E, N);
    scatter_eid_kernel<<<(E + 255) / 256, 256, 0, s2>>>(src, dst, E);
    cudaEventRecord(evJoin, s2);

    // node GEMM (hf, el, er, fp16 shadow) on main stream, concurrent with CSR
    gemm128_kernel<0><<<(N + 63) / 64, 256, SMEM>>>(
        nfeat, W_fc, N, attn_l, attn_r, nullptr, nullptr, nullptr);

    // ---- join: gather needs both CSR and GEMM0 ----
    cudaStreamWaitEvent(0, evJoin, 0);

    // fused softmax + aggregation + edge-feature sum
    gather_kernel<<<(N * 32 + 255) / 256, 256>>>(efeat, N);

    // edge GEMM (reordered through segment-sum) + final combine
    gemm128_kernel<1><<<(N + 63) / 64, 256, SMEM>>>(
        nullptr, W_e, N, nullptr, nullptr, bias, b_e, out);
}